// round 1
// baseline (speedup 1.0000x reference)
#include <cuda_runtime.h>
#include <cstdint>
#include <cstddef>

// ---------------------------------------------------------------------------
// HybridKernelTransformer — collapsed form.
// x is dead (kern == 1), S == 1 (softmax trivial), h0 = [1,2,1,2,...].
// Per block i:
//   proj = cos(hn_prev[0:8] + phi_q[i]);  v = Wv[i] @ proj
//   attn = Wo[i] @ v;  pre1 = hn_prev + attn;  hn1 = LN(pre1; ln1[i])
//   m4 = cos(hn1[0:4]) * cos(phi_f[i]);  r = relu(W1[i] @ m4)
//   f  = W2[i] @ r;    pre2 = hn1 + f;   hn2 = LN(pre2; ln2[i])
// Final: y[c] = Wc[c,:] @ hn2_final + bc[c]; out[b,:] = y for all b.
// LN stats are carried as per-CTA double partials, summed deterministically
// by the consumer (fixed tree order) -> bitwise-deterministic replays.
// ---------------------------------------------------------------------------

#define E    1024
#define FF   4096
#define NBLK 6
#define GA   128   // CTAs for attn kernel (8 warps * 128 = 1024 rows)
#define GF   128   // CTAs for ffn kernel

__device__ __align__(16) float g_bufA[E];          // pre-ln1 values of current block
__device__ __align__(16) float g_bufB[E];          // pre-ln2 values of current block
__device__ double g_part1[NBLK][GA][2];            // (sum, sumsq) partials for ln1
__device__ double g_part2[NBLK][GF][2];            // (sum, sumsq) partials for ln2
__device__ __align__(16) float g_y[1000];

// Deterministic reduction of 128 (sum,sumsq) double pairs -> mean, inv_std.
// Uses warps 0..3 (tid<128) with shfl tree + fixed-order final sum.
__device__ __forceinline__ void load_stats(const double* __restrict__ p,
                                           float* s_mi, double* s_red, int tid)
{
    int lane = tid & 31, warp = tid >> 5;
    if (tid < 128) {
        double s = p[2 * tid], q = p[2 * tid + 1];
        #pragma unroll
        for (int o = 16; o; o >>= 1) {
            s += __shfl_xor_sync(0xffffffffu, s, o);
            q += __shfl_xor_sync(0xffffffffu, q, o);
        }
        if (lane == 0) { s_red[warp * 2] = s; s_red[warp * 2 + 1] = q; }
    }
    __syncthreads();
    if (tid == 0) {
        double s = 0.0, q = 0.0;
        #pragma unroll
        for (int w = 0; w < 4; w++) { s += s_red[w * 2]; q += s_red[w * 2 + 1]; }
        double m   = s * (1.0 / 1024.0);
        double var = q * (1.0 / 1024.0) - m * m;
        s_mi[0] = (float)m;
        s_mi[1] = (float)rsqrt(var + 1e-5);
    }
    __syncthreads();
}

// ------------------------- attention kernel --------------------------------
// grid GA=128, block 256. warp w of CTA b owns row e = b*8+w of attn = Wo@v.
__global__ void __launch_bounds__(256)
attn_kernel(int blk,
            const float* __restrict__ Wv,   // (6, E, 8)
            const float* __restrict__ Wo,   // (6, E, E)
            const float* __restrict__ phiq, // (6, 8)
            const float* __restrict__ ln2g, // (6, E)  (prev block's ln2)
            const float* __restrict__ ln2b)
{
    __shared__ __align__(16) float sh[E];   // normalized previous h
    __shared__ __align__(16) float sv[E];   // v vector
    __shared__ float  sred[8];
    __shared__ float  s_mi[2];
    __shared__ double s_red[8];

    int tid = threadIdx.x;

    if (blk == 0) {
        for (int e = tid; e < E; e += 256) sh[e] = (e & 1) ? 2.0f : 1.0f;
        __syncthreads();
    } else {
        load_stats(&g_part2[blk - 1][0][0], s_mi, s_red, tid);
        float mn = s_mi[0], inv = s_mi[1];
        const float* gg = ln2g + (size_t)(blk - 1) * E;
        const float* bb = ln2b + (size_t)(blk - 1) * E;
        for (int e = tid; e < E; e += 256)
            sh[e] = (g_bufB[e] - mn) * inv * gg[e] + bb[e];
        __syncthreads();
    }

    // proj (8 values, computed redundantly per thread — trivial)
    float proj[8];
    #pragma unroll
    for (int w = 0; w < 8; w++) proj[w] = cosf(sh[w] + phiq[blk * 8 + w]);

    // v = Wv[blk] @ proj
    const float4* Wv4 = (const float4*)(Wv + (size_t)blk * E * 8);
    for (int e = tid; e < E; e += 256) {
        float4 a = Wv4[e * 2], b2 = Wv4[e * 2 + 1];
        sv[e] = a.x * proj[0] + a.y * proj[1] + a.z * proj[2] + a.w * proj[3]
              + b2.x * proj[4] + b2.y * proj[5] + b2.z * proj[6] + b2.w * proj[7];
    }
    __syncthreads();

    // warp-per-row dot: attn[e] = Wo[blk][e,:] . v
    int warp = tid >> 5, lane = tid & 31;
    int e = blockIdx.x * 8 + warp;
    const float4* row = (const float4*)(Wo + (size_t)blk * E * E + (size_t)e * E);
    const float4* sv4 = (const float4*)sv;
    float acc = 0.0f;
    #pragma unroll
    for (int k = 0; k < 8; k++) {
        float4 w4 = row[lane + 32 * k];
        float4 v4 = sv4[lane + 32 * k];
        acc += w4.x * v4.x + w4.y * v4.y + w4.z * v4.z + w4.w * v4.w;
    }
    #pragma unroll
    for (int o = 16; o; o >>= 1) acc += __shfl_xor_sync(0xffffffffu, acc, o);

    if (lane == 0) {
        float outv = sh[e] + acc;
        g_bufA[e] = outv;
        sred[warp] = outv;
    }
    __syncthreads();
    if (tid == 0) {
        double s = 0.0, q = 0.0;
        #pragma unroll
        for (int w = 0; w < 8; w++) { double v = (double)sred[w]; s += v; q += v * v; }
        g_part1[blk][blockIdx.x][0] = s;
        g_part1[blk][blockIdx.x][1] = q;
    }
}

// ------------------------- feedforward kernel ------------------------------
// grid GF=128, block 256. warp w of CTA b owns row e = b*8+w of f = W2@r.
__global__ void __launch_bounds__(256)
ff_kernel(int blk,
          const float* __restrict__ W1,    // (6, FF, 4)
          const float* __restrict__ W2,    // (6, E, FF)
          const float* __restrict__ phif,  // (6, 4)
          const float* __restrict__ ln1g,  // (6, E)
          const float* __restrict__ ln1b)
{
    __shared__ __align__(16) float sh[E];
    __shared__ __align__(16) float sr[FF];
    __shared__ float  sred[8];
    __shared__ float  s_mi[2];
    __shared__ double s_red[8];

    int tid = threadIdx.x;

    load_stats(&g_part1[blk][0][0], s_mi, s_red, tid);
    float mn = s_mi[0], inv = s_mi[1];
    const float* gg = ln1g + (size_t)blk * E;
    const float* bb = ln1b + (size_t)blk * E;
    for (int e = tid; e < E; e += 256)
        sh[e] = (g_bufA[e] - mn) * inv * gg[e] + bb[e];
    __syncthreads();

    float m4[4];
    #pragma unroll
    for (int w = 0; w < 4; w++) m4[w] = cosf(sh[w]) * cosf(phif[blk * 4 + w]);

    // r = relu(W1[blk] @ m4)   (FF=4096 outputs, 4-wide dot each)
    const float4* W14 = (const float4*)(W1 + (size_t)blk * FF * 4);
    for (int j = tid; j < FF; j += 256) {
        float4 w = W14[j];
        float t = w.x * m4[0] + w.y * m4[1] + w.z * m4[2] + w.w * m4[3];
        sr[j] = fmaxf(t, 0.0f);
    }
    __syncthreads();

    // warp-per-row dot: f[e] = W2[blk][e,:] . r   (4096-wide)
    int warp = tid >> 5, lane = tid & 31;
    int e = blockIdx.x * 8 + warp;
    const float4* row = (const float4*)(W2 + (size_t)blk * E * FF + (size_t)e * FF);
    const float4* sr4 = (const float4*)sr;
    float acc = 0.0f;
    #pragma unroll
    for (int k = 0; k < 32; k++) {
        float4 w4 = row[lane + 32 * k];
        float4 r4 = sr4[lane + 32 * k];
        acc += w4.x * r4.x + w4.y * r4.y + w4.z * r4.z + w4.w * r4.w;
    }
    #pragma unroll
    for (int o = 16; o; o >>= 1) acc += __shfl_xor_sync(0xffffffffu, acc, o);

    if (lane == 0) {
        float outv = sh[e] + acc;
        g_bufB[e] = outv;
        sred[warp] = outv;
    }
    __syncthreads();
    if (tid == 0) {
        double s = 0.0, q = 0.0;
        #pragma unroll
        for (int w = 0; w < 8; w++) { double v = (double)sred[w]; s += v; q += v * v; }
        g_part2[blk][blockIdx.x][0] = s;
        g_part2[blk][blockIdx.x][1] = q;
    }
}

// ------------------------- classifier head ---------------------------------
// grid 125, block 256 -> 1000 warps, warp per class c.
__global__ void __launch_bounds__(256)
y_kernel(const float* __restrict__ Wc,    // (1000, E)
         const float* __restrict__ bc,    // (1000,)
         const float* __restrict__ ln2g,
         const float* __restrict__ ln2b)
{
    __shared__ __align__(16) float sh[E];
    __shared__ float  s_mi[2];
    __shared__ double s_red[8];

    int tid = threadIdx.x;
    load_stats(&g_part2[NBLK - 1][0][0], s_mi, s_red, tid);
    float mn = s_mi[0], inv = s_mi[1];
    const float* gg = ln2g + (size_t)(NBLK - 1) * E;
    const float* bb = ln2b + (size_t)(NBLK - 1) * E;
    for (int e = tid; e < E; e += 256)
        sh[e] = (g_bufB[e] - mn) * inv * gg[e] + bb[e];
    __syncthreads();

    int warp = tid >> 5, lane = tid & 31;
    int c = blockIdx.x * 8 + warp;           // 0..999 exactly
    const float4* row = (const float4*)(Wc + (size_t)c * E);
    const float4* sh4 = (const float4*)sh;
    float acc = 0.0f;
    #pragma unroll
    for (int k = 0; k < 8; k++) {
        float4 w4 = row[lane + 32 * k];
        float4 h4 = sh4[lane + 32 * k];
        acc += w4.x * h4.x + w4.y * h4.y + w4.z * h4.z + w4.w * h4.w;
    }
    #pragma unroll
    for (int o = 16; o; o >>= 1) acc += __shfl_xor_sync(0xffffffffu, acc, o);
    if (lane == 0) g_y[c] = acc + bc[c];
}

// ------------------------- broadcast ----------------------------------------
// out[b, :] = y for all b. grid 256, block 256, 16 rows per CTA, float4 stores.
__global__ void __launch_bounds__(256)
bcast_kernel(float* __restrict__ out)
{
    __shared__ __align__(16) float4 sy[250];
    int tid = threadIdx.x;
    if (tid < 250) sy[tid] = ((const float4*)g_y)[tid];
    __syncthreads();
    int base = blockIdx.x * 16;
    #pragma unroll
    for (int r = 0; r < 16; r++) {
        if (tid < 250)
            ((float4*)(out + (size_t)(base + r) * 1000))[tid] = sy[tid];
    }
}

// ---------------------------------------------------------------------------
extern "C" void kernel_launch(void* const* d_in, const int* in_sizes, int n_in,
                              void* d_out, int out_size)
{
    // metadata order: x, Wq, Wk, Wv, Wo, phi_q, W1, W2, phi_f,
    //                 ln1_g, ln1_b, ln2_g, ln2_b, Wc, bc
    const float* Wv   = (const float*)d_in[3];
    const float* Wo   = (const float*)d_in[4];
    const float* phiq = (const float*)d_in[5];
    const float* W1   = (const float*)d_in[6];
    const float* W2   = (const float*)d_in[7];
    const float* phif = (const float*)d_in[8];
    const float* ln1g = (const float*)d_in[9];
    const float* ln1b = (const float*)d_in[10];
    const float* ln2g = (const float*)d_in[11];
    const float* ln2b = (const float*)d_in[12];
    const float* Wc   = (const float*)d_in[13];
    const float* bc   = (const float*)d_in[14];
    float* out = (float*)d_out;

    for (int i = 0; i < NBLK; i++) {
        attn_kernel<<<GA, 256>>>(i, Wv, Wo, phiq, ln2g, ln2b);
        ff_kernel<<<GF, 256>>>(i, W1, W2, phif, ln1g, ln1b);
    }
    y_kernel<<<125, 256>>>(Wc, bc, ln2g, ln2b);
    bcast_kernel<<<256, 256>>>(out);
}

// round 4
// speedup vs baseline: 1.4473x; 1.4473x over previous
#include <cuda_runtime.h>
#include <cstdint>
#include <cstddef>

// ---------------------------------------------------------------------------
// Collapsed HybridKernelTransformer (x dead, S==1, h0=[1,2,1,2,...]).
// Per block i:
//   prep_a: stats(ln2 prev) -> g_hn, proj, g_v
//   attn  : g_bufA[e] = g_hn[e] + Wo[i][e,:].g_v          (streams 4MB)
//   prep_f: stats(ln1) -> g_hn1, m4, g_r = relu(W1@m4)
//   ff    : g_bufB[e] = g_hn1[e] + W2[i][e,:].g_r         (streams 16MB)
// Tail: y_kernel (per-CTA final LN + Wc matvec) ; broadcast to 4096 rows.
// All LN reductions use a fixed order -> bitwise-deterministic replays.
// ---------------------------------------------------------------------------

#define E    1024
#define FF   4096
#define NBLK 6

__device__ __align__(16) float g_hn[E];    // normalized h entering block
__device__ __align__(16) float g_v[E];     // v vector
__device__ __align__(16) float g_bufA[E];  // pre-ln1
__device__ __align__(16) float g_hn1[E];   // normalized after ln1
__device__ __align__(16) float g_r[FF];    // relu(W1@m4)
__device__ __align__(16) float g_bufB[E];  // pre-ln2
__device__ __align__(16) float g_y[1000];

// Deterministic single-CTA (256 thr) stats over a 1024-float global vector.
// Result in s_mi[0]=mean, s_mi[1]=inv_std. Fixed reduction order.
__device__ __forceinline__ void cta_stats(const float* __restrict__ v,
                                          float* s_mi, double* s_red, int tid)
{
    int lane = tid & 31, warp = tid >> 5;
    double s = 0.0, q = 0.0;
    #pragma unroll
    for (int k = 0; k < 4; k++) {
        double x = (double)v[tid * 4 + k];
        s += x; q += x * x;
    }
    #pragma unroll
    for (int o = 16; o; o >>= 1) {
        s += __shfl_xor_sync(0xffffffffu, s, o);
        q += __shfl_xor_sync(0xffffffffu, q, o);
    }
    if (lane == 0) { s_red[warp * 2] = s; s_red[warp * 2 + 1] = q; }
    __syncthreads();
    if (tid == 0) {
        double ss = 0.0, qq = 0.0;
        #pragma unroll
        for (int w = 0; w < 8; w++) { ss += s_red[w * 2]; qq += s_red[w * 2 + 1]; }
        double m   = ss * (1.0 / 1024.0);
        double var = qq * (1.0 / 1024.0) - m * m;
        s_mi[0] = (float)m;
        s_mi[1] = (float)rsqrt(var + 1e-5);
    }
    __syncthreads();
}

// ------------------------- prep_a: g_hn, g_v --------------------------------
__global__ void __launch_bounds__(256)
prep_a(int blk,
       const float* __restrict__ Wv,    // (6, E, 8)
       const float* __restrict__ phiq,  // (6, 8)
       const float* __restrict__ ln2g,  // (6, E)
       const float* __restrict__ ln2b)
{
    __shared__ __align__(16) float sh[E];
    __shared__ float  s_mi[2];
    __shared__ double s_red[16];
    int tid = threadIdx.x;

    if (blk == 0) {
        #pragma unroll
        for (int k = 0; k < 4; k++) {
            int e = tid * 4 + k;
            float v = (e & 1) ? 2.0f : 1.0f;
            sh[e] = v; g_hn[e] = v;
        }
        __syncthreads();
    } else {
        cta_stats(g_bufB, s_mi, s_red, tid);
        float mn = s_mi[0], inv = s_mi[1];
        const float* gg = ln2g + (size_t)(blk - 1) * E;
        const float* bb = ln2b + (size_t)(blk - 1) * E;
        #pragma unroll
        for (int k = 0; k < 4; k++) {
            int e = tid * 4 + k;
            float v = (g_bufB[e] - mn) * inv * gg[e] + bb[e];
            sh[e] = v; g_hn[e] = v;
        }
        __syncthreads();
    }

    float proj[8];
    #pragma unroll
    for (int w = 0; w < 8; w++) proj[w] = cosf(sh[w] + phiq[blk * 8 + w]);

    const float4* Wv4 = (const float4*)(Wv + (size_t)blk * E * 8);
    #pragma unroll
    for (int k = 0; k < 4; k++) {
        int e = tid + 256 * k;
        float4 a = Wv4[e * 2], b2 = Wv4[e * 2 + 1];
        g_v[e] = a.x * proj[0] + a.y * proj[1] + a.z * proj[2] + a.w * proj[3]
               + b2.x * proj[4] + b2.y * proj[5] + b2.z * proj[6] + b2.w * proj[7];
    }
}

// ------------------------- attn: stream Wo ----------------------------------
// grid 512, block 256: CTA b owns rows e0=2b, e0+1.
__global__ void __launch_bounds__(256)
attn_kernel(int blk, const float* __restrict__ Wo)
{
    __shared__ __align__(16) float4 sv4[E / 4];
    __shared__ float sred0[8], sred1[8];
    int tid = threadIdx.x;
    sv4[tid] = ((const float4*)g_v)[tid];
    __syncthreads();

    int e0 = blockIdx.x * 2;
    const float4* r0 = (const float4*)(Wo + (size_t)blk * E * E + (size_t)e0 * E);
    const float4* r1 = r0 + E / 4;

    float4 w0 = r0[tid];
    float4 w1 = r1[tid];
    float4 vv = sv4[tid];
    float acc0 = w0.x * vv.x + w0.y * vv.y + w0.z * vv.z + w0.w * vv.w;
    float acc1 = w1.x * vv.x + w1.y * vv.y + w1.z * vv.z + w1.w * vv.w;

    #pragma unroll
    for (int o = 16; o; o >>= 1) {
        acc0 += __shfl_xor_sync(0xffffffffu, acc0, o);
        acc1 += __shfl_xor_sync(0xffffffffu, acc1, o);
    }
    int warp = tid >> 5, lane = tid & 31;
    if (lane == 0) { sred0[warp] = acc0; sred1[warp] = acc1; }
    __syncthreads();
    if (tid == 0) {
        float s = 0.0f;
        #pragma unroll
        for (int w = 0; w < 8; w++) s += sred0[w];
        g_bufA[e0] = g_hn[e0] + s;
    }
    if (tid == 1) {
        float s = 0.0f;
        #pragma unroll
        for (int w = 0; w < 8; w++) s += sred1[w];
        g_bufA[e0 + 1] = g_hn[e0 + 1] + s;
    }
}

// ------------------------- prep_f: g_hn1, g_r -------------------------------
__global__ void __launch_bounds__(256)
prep_f(int blk,
       const float* __restrict__ W1,    // (6, FF, 4)
       const float* __restrict__ phif,  // (6, 4)
       const float* __restrict__ ln1g,
       const float* __restrict__ ln1b)
{
    __shared__ float sh4[4];
    __shared__ float  s_mi[2];
    __shared__ double s_red[16];
    int tid = threadIdx.x;

    cta_stats(g_bufA, s_mi, s_red, tid);
    float mn = s_mi[0], inv = s_mi[1];
    const float* gg = ln1g + (size_t)blk * E;
    const float* bb = ln1b + (size_t)blk * E;
    #pragma unroll
    for (int k = 0; k < 4; k++) {
        int e = tid * 4 + k;
        float v = (g_bufA[e] - mn) * inv * gg[e] + bb[e];
        g_hn1[e] = v;
        if (e < 4) sh4[e] = v;
    }
    __syncthreads();

    float m4[4];
    #pragma unroll
    for (int w = 0; w < 4; w++) m4[w] = cosf(sh4[w]) * cosf(phif[blk * 4 + w]);

    const float4* W14 = (const float4*)(W1 + (size_t)blk * FF * 4);
    #pragma unroll
    for (int k = 0; k < 16; k++) {
        int j = tid + 256 * k;
        float4 w = W14[j];
        float t = w.x * m4[0] + w.y * m4[1] + w.z * m4[2] + w.w * m4[3];
        g_r[j] = fmaxf(t, 0.0f);
    }
}

// ------------------------- ff: stream W2 ------------------------------------
// grid 512, block 256: CTA b owns rows e0=2b, e0+1; 4 float4/thread/row.
// g_r is read straight from L2 (16KB written once, hot for all CTAs).
__global__ void __launch_bounds__(256)
ff_kernel(int blk, const float* __restrict__ W2)
{
    __shared__ float sred0[8], sred1[8];
    int tid = threadIdx.x;

    int e0 = blockIdx.x * 2;
    const float4* r0 = (const float4*)(W2 + (size_t)blk * E * FF + (size_t)e0 * FF);
    const float4* r1 = r0 + FF / 4;
    const float4* gr4 = (const float4*)g_r;

    float acc0 = 0.0f, acc1 = 0.0f;
    #pragma unroll
    for (int k = 0; k < 4; k++) {
        int j = tid + 256 * k;
        float4 w0 = r0[j];
        float4 w1 = r1[j];
        float4 rr = __ldg(&gr4[j]);
        acc0 += w0.x * rr.x + w0.y * rr.y + w0.z * rr.z + w0.w * rr.w;
        acc1 += w1.x * rr.x + w1.y * rr.y + w1.z * rr.z + w1.w * rr.w;
    }

    #pragma unroll
    for (int o = 16; o; o >>= 1) {
        acc0 += __shfl_xor_sync(0xffffffffu, acc0, o);
        acc1 += __shfl_xor_sync(0xffffffffu, acc1, o);
    }
    int warp = tid >> 5, lane = tid & 31;
    if (lane == 0) { sred0[warp] = acc0; sred1[warp] = acc1; }
    __syncthreads();
    if (tid == 0) {
        float s = 0.0f;
        #pragma unroll
        for (int w = 0; w < 8; w++) s += sred0[w];
        g_bufB[e0] = g_hn1[e0] + s;
    }
    if (tid == 1) {
        float s = 0.0f;
        #pragma unroll
        for (int w = 0; w < 8; w++) s += sred1[w];
        g_bufB[e0 + 1] = g_hn1[e0 + 1] + s;
    }
}

// ------------------------- classifier head ----------------------------------
// grid 500, block 256: CTA b owns classes c0=2b, c0+1.
// Final LN computed per-CTA (redundant but deterministic, removes prep_y).
__global__ void __launch_bounds__(256)
y_kernel(const float* __restrict__ Wc, const float* __restrict__ bc,
         const float* __restrict__ ln2g, const float* __restrict__ ln2b)
{
    __shared__ __align__(16) float sh[E];
    __shared__ float  s_mi[2];
    __shared__ double s_red[16];
    __shared__ float sred0[8], sred1[8];
    int tid = threadIdx.x;

    cta_stats(g_bufB, s_mi, s_red, tid);
    float mn = s_mi[0], inv = s_mi[1];
    const float* gg = ln2g + (size_t)(NBLK - 1) * E;
    const float* bb = ln2b + (size_t)(NBLK - 1) * E;
    #pragma unroll
    for (int k = 0; k < 4; k++) {
        int e = tid * 4 + k;
        sh[e] = (g_bufB[e] - mn) * inv * gg[e] + bb[e];
    }
    __syncthreads();

    int c0 = blockIdx.x * 2;
    const float4* r0 = (const float4*)(Wc + (size_t)c0 * E);
    const float4* r1 = r0 + E / 4;
    const float4* sh4 = (const float4*)sh;

    float4 w0 = r0[tid];
    float4 w1 = r1[tid];
    float4 hh = sh4[tid];
    float acc0 = w0.x * hh.x + w0.y * hh.y + w0.z * hh.z + w0.w * hh.w;
    float acc1 = w1.x * hh.x + w1.y * hh.y + w1.z * hh.z + w1.w * hh.w;

    #pragma unroll
    for (int o = 16; o; o >>= 1) {
        acc0 += __shfl_xor_sync(0xffffffffu, acc0, o);
        acc1 += __shfl_xor_sync(0xffffffffu, acc1, o);
    }
    int warp = tid >> 5, lane = tid & 31;
    if (lane == 0) { sred0[warp] = acc0; sred1[warp] = acc1; }
    __syncthreads();
    if (tid == 0) {
        float s = 0.0f;
        #pragma unroll
        for (int w = 0; w < 8; w++) s += sred0[w];
        g_y[c0] = s + bc[c0];
    }
    if (tid == 1) {
        float s = 0.0f;
        #pragma unroll
        for (int w = 0; w < 8; w++) s += sred1[w];
        g_y[c0 + 1] = s + bc[c0 + 1];
    }
}

// ------------------------- broadcast ----------------------------------------
__global__ void __launch_bounds__(256)
bcast_kernel(float* __restrict__ out)
{
    __shared__ __align__(16) float4 sy[250];
    int tid = threadIdx.x;
    if (tid < 250) sy[tid] = ((const float4*)g_y)[tid];
    __syncthreads();
    int base = blockIdx.x * 8;
    #pragma unroll
    for (int r = 0; r < 8; r++) {
        if (tid < 250)
            ((float4*)(out + (size_t)(base + r) * 1000))[tid] = sy[tid];
    }
}

// ---------------------------------------------------------------------------
extern "C" void kernel_launch(void* const* d_in, const int* in_sizes, int n_in,
                              void* d_out, int out_size)
{
    // metadata order: x, Wq, Wk, Wv, Wo, phi_q, W1, W2, phi_f,
    //                 ln1_g, ln1_b, ln2_g, ln2_b, Wc, bc
    const float* Wv   = (const float*)d_in[3];
    const float* Wo   = (const float*)d_in[4];
    const float* phiq = (const float*)d_in[5];
    const float* W1   = (const float*)d_in[6];
    const float* W2   = (const float*)d_in[7];
    const float* phif = (const float*)d_in[8];
    const float* ln1g = (const float*)d_in[9];
    const float* ln1b = (const float*)d_in[10];
    const float* ln2g = (const float*)d_in[11];
    const float* ln2b = (const float*)d_in[12];
    const float* Wc   = (const float*)d_in[13];
    const float* bc   = (const float*)d_in[14];
    float* out = (float*)d_out;

    for (int i = 0; i < NBLK; i++) {
        prep_a<<<1, 256>>>(i, Wv, phiq, ln2g, ln2b);
        attn_kernel<<<512, 256>>>(i, Wo);
        prep_f<<<1, 256>>>(i, W1, phif, ln1g, ln1b);
        ff_kernel<<<512, 256>>>(i, W2);
    }
    y_kernel<<<500, 256>>>(Wc, bc, ln2g, ln2b);
    bcast_kernel<<<512, 256>>>(out);
}